// round 10
// baseline (speedup 1.0000x reference)
#include <cuda_runtime.h>
#include <cstdint>
#include <cstddef>

// Fixed shapes: B=1, N=1000, T=256, D=512, M=258, NUM=10
// out row = 3082 floats (12328 B; 16B-aligned only for even n)
#define N_CAND   1000
#define T_DIM    256
#define D_DIM    512
#define M_DIM    258
#define NUMF     10
#define ROW_OUT  3082
#define R4       (D_DIM / 4)       // 128 float4 per 512-float section

// One block per candidate, 128 threads. Each thread copies float4 lane `t`
// of ALL six sections: 6 independent LDG.128 (front-batched by ptxas, MLP=6
// per thread, ~3 KB in flight per warp), then 6 (even rows) or 12 (odd rows)
// stores chosen by output-row parity.
__global__ __launch_bounds__(128) void feature_gather_final(
    const int* __restrict__ cand,        // [N,6]
    const float* __restrict__ num,       // [N,10]
    const float* __restrict__ blo,       // [N,T,D]
    const float* __restrict__ att,       // [N,M,D]
    float* __restrict__ out)             // [N,3082]
{
    const int n = blockIdx.x;
    const int t = threadIdx.x;           // float4 lane 0..127

    // Candidate indices (tiny array, L2-hot, L1 broadcast within the block).
    const int2* cp = (const int2*)(cand + n * 6);
    const int2 p01 = __ldg(cp + 0);      // c0, c1
    const int2 p23 = __ldg(cp + 1);      // c2, c3
    const int2 p45 = __ldg(cp + 2);      // c4, c5

    const float4* b4 = (const float4*)(blo + (size_t)n * T_DIM * D_DIM);
    const float4* a4 = (const float4*)(att + (size_t)n * M_DIM * D_DIM);

    // Six independent gather loads; no volatile so ptxas can front-batch
    // all six LDG.128 before the first consumer.
    const float4 v0 = __ldg(b4 + (size_t)p01.y * R4 + t);        // blo[c1]
    const float4 v1 = __ldg(b4 + (size_t)p23.x * R4 + t);        // blo[c2]
    const float4 v2 = __ldg(b4 + (size_t)p45.x * R4 + t);        // blo[c4]
    const float4 v3 = __ldg(b4 + (size_t)p45.y * R4 + t);        // blo[c5]
    const float4 v4 = __ldg(a4 + (size_t)(p01.x + 2) * R4 + t);  // att[c0+2]
    const float4 v5 = __ldg(a4 + (size_t)(p23.y + 2) * R4 + t);  // att[c3+2]

    float* outRow = out + (size_t)n * ROW_OUT;

    if ((n & 1) == 0) {
        float4* o4 = (float4*)outRow;    // 16B-aligned row: STG.128 x6
        o4[0 * R4 + t] = v0;
        o4[1 * R4 + t] = v1;
        o4[2 * R4 + t] = v2;
        o4[3 * R4 + t] = v3;
        o4[4 * R4 + t] = v4;
        o4[5 * R4 + t] = v5;
    } else {
        float2* o2 = (float2*)outRow;    // 8B-aligned row: STG.64 x12
        #define ST2(s, v)                                            \
            o2[((s) * R4 + t) * 2]     = make_float2((v).x, (v).y);  \
            o2[((s) * R4 + t) * 2 + 1] = make_float2((v).z, (v).w);
        ST2(0, v0) ST2(1, v1) ST2(2, v2) ST2(3, v3) ST2(4, v4) ST2(5, v5)
        #undef ST2
    }

    // Numeric features: 10 floats = 5 float2, threads 0..4.
    if (t < NUMF / 2) {
        const float2* num2 = (const float2*)(num + (size_t)n * NUMF);
        ((float2*)outRow)[6 * (D_DIM / 2) + t] = __ldg(num2 + t);
    }
}

extern "C" void kernel_launch(void* const* d_in, const int* in_sizes, int n_in,
                              void* d_out, int out_size) {
    const int*   cand = (const int*)d_in[0];
    const float* num  = (const float*)d_in[1];
    const float* blo  = (const float*)d_in[2];
    const float* att  = (const float*)d_in[3];
    float* out = (float*)d_out;

    feature_gather_final<<<N_CAND, 128>>>(cand, num, blo, att, out);
}